// round 2
// baseline (speedup 1.0000x reference)
#include <cuda_runtime.h>

// QuantumAttention: B=16384 samples. One warp per sample.
// Score circuit (8 qubits, 256 amps): 8 float2 per lane, amp index = (lane<<3)|r.
//   Bits 0..2 of the amplitude index are "local" (register index r),
//   bits 3..7 are "lane bits" (lane bit LB = bit-3).
// Value circuit (4 qubits, 16 amps): one amp per lane, idx = lane & 15
//   (state duplicated across both half-warps; xor-shfl masks < 16 keep halves consistent).
// Wire w of an n-wire register maps to bit (n-1-w).

#define IN_DIM 96
#define WPB 8
#define FULL 0xffffffffu

// ---- precomputed trig table for shared circuit parameters ----
__device__ float2 g_trig[68];

#define T_WQ_ROT 0
#define T_WQ_CRX 12
#define T_WK_ROT 16
#define T_WK_CRX 28
#define T_WV_ROT 32
#define T_WV_CRX 44
#define T_WC_ROT 48
#define T_WC_CRX 60

__global__ void prep_kernel(const float* __restrict__ wq_rot, const float* __restrict__ wq_crx,
                            const float* __restrict__ wk_rot, const float* __restrict__ wk_crx,
                            const float* __restrict__ wv_rot, const float* __restrict__ wv_crx,
                            const float* __restrict__ wc_rot, const float* __restrict__ wc_crx) {
    int t = threadIdx.x;
    float ang;
    if      (t < 12) ang = wq_rot[t];
    else if (t < 16) ang = wq_crx[t - 12];
    else if (t < 28) ang = wk_rot[t - 16];
    else if (t < 32) ang = wk_crx[t - 28];
    else if (t < 44) ang = wv_rot[t - 32];
    else if (t < 48) ang = wv_crx[t - 44];
    else if (t < 60) ang = wc_rot[t - 48];
    else if (t < 68) ang = wc_crx[t - 60];
    else return;
    float s, c;
    sincosf(0.5f * ang, &s, &c);
    g_trig[t] = make_float2(c, s);
}

__device__ __forceinline__ float2 trig(int i) {
    return __ldg(((const float2*)g_trig) + i);
}

// ---- primitives ----

__device__ __forceinline__ float2 shfl2(float2 a, int m) {
    return make_float2(__shfl_xor_sync(FULL, a.x, m), __shfl_xor_sync(FULL, a.y, m));
}

// RX pair update for the "self" amplitude: new = c*self - i*s*other
__device__ __forceinline__ float2 rxmix(float2 a, float2 o, float c, float s) {
    return make_float2(fmaf(c, a.x, s * o.y), fmaf(c, a.y, -s * o.x));
}

__device__ __forceinline__ float warp_reduce(float v) {
#pragma unroll
    for (int o = 16; o; o >>= 1) v += __shfl_xor_sync(FULL, v, o);
    return v;
}

// ---- 8-qubit (256 amp) gates on v[8] ----

template<int LB>
__device__ __forceinline__ void rx_cross(float2 (&v)[8], float c, float s) {
#pragma unroll
    for (int r = 0; r < 8; r++) {
        float2 o = shfl2(v[r], 1 << LB);
        v[r] = rxmix(v[r], o, c, s);
    }
}

template<int B>
__device__ __forceinline__ void rx_local(float2 (&v)[8], float c, float s) {
#pragma unroll
    for (int r = 0; r < 8; r++) if (!(r & (1 << B))) {
        int r1 = r | (1 << B);
        float2 a0 = v[r], a1 = v[r1];
        v[r]  = rxmix(a0, a1, c, s);
        v[r1] = rxmix(a1, a0, c, s);
    }
}

// RZ: amp *= e^{-i t/2} if bit==0 else e^{+i t/2}; new = (c*x - sgn*y, c*y + sgn*x), sgn = bit ? s : -s
template<int LB>
__device__ __forceinline__ void rz_cross(float2 (&v)[8], float c, float s, int lane) {
    float sgn = ((lane >> LB) & 1) ? s : -s;
#pragma unroll
    for (int r = 0; r < 8; r++) {
        float2 a = v[r];
        v[r] = make_float2(fmaf(c, a.x, -sgn * a.y), fmaf(c, a.y, sgn * a.x));
    }
}

template<int B>
__device__ __forceinline__ void rz_local(float2 (&v)[8], float c, float s) {
#pragma unroll
    for (int r = 0; r < 8; r++) {
        float sgn = ((r >> B) & 1) ? s : -s;
        float2 a = v[r];
        v[r] = make_float2(fmaf(c, a.x, -sgn * a.y), fmaf(c, a.y, sgn * a.x));
    }
}

// CRX variants: control bit (c) / target bit (t); each either lane bit (LB*) or local bit (B*)
template<int LBc, int LBt>
__device__ __forceinline__ void crx_cc(float2 (&v)[8], float c, float s, int lane) {
    bool ct = (lane >> LBc) & 1;
#pragma unroll
    for (int r = 0; r < 8; r++) {
        float2 o = shfl2(v[r], 1 << LBt);
        float2 m = rxmix(v[r], o, c, s);
        v[r] = ct ? m : v[r];
    }
}

template<int LBc, int Bt>
__device__ __forceinline__ void crx_cl(float2 (&v)[8], float c, float s, int lane) {
    bool ct = (lane >> LBc) & 1;
#pragma unroll
    for (int r = 0; r < 8; r++) if (!(r & (1 << Bt))) {
        int r1 = r | (1 << Bt);
        float2 a0 = v[r], a1 = v[r1];
        float2 m0 = rxmix(a0, a1, c, s);
        float2 m1 = rxmix(a1, a0, c, s);
        v[r]  = ct ? m0 : a0;
        v[r1] = ct ? m1 : a1;
    }
}

template<int Bc, int LBt>
__device__ __forceinline__ void crx_lc(float2 (&v)[8], float c, float s) {
#pragma unroll
    for (int r = 0; r < 8; r++) if ((r >> Bc) & 1) {
        float2 o = shfl2(v[r], 1 << LBt);
        v[r] = rxmix(v[r], o, c, s);
    }
}

template<int Bc, int Bt>
__device__ __forceinline__ void crx_ll(float2 (&v)[8], float c, float s) {
#pragma unroll
    for (int r = 0; r < 8; r++) if (((r >> Bc) & 1) && !((r >> Bt) & 1)) {
        int r1 = r | (1 << Bt);
        float2 a0 = v[r], a1 = v[r1];
        v[r]  = rxmix(a0, a1, c, s);
        v[r1] = rxmix(a1, a0, c, s);
    }
}

// CNOT variants
template<int LBc, int LBt>
__device__ __forceinline__ void cnot_cc(float2 (&v)[8], int lane) {
    bool ct = (lane >> LBc) & 1;
#pragma unroll
    for (int r = 0; r < 8; r++) {
        float2 o = shfl2(v[r], 1 << LBt);
        v[r] = ct ? o : v[r];
    }
}

template<int LBc, int Bt>
__device__ __forceinline__ void cnot_cl(float2 (&v)[8], int lane) {
    bool ct = (lane >> LBc) & 1;
#pragma unroll
    for (int r = 0; r < 8; r++) if (!(r & (1 << Bt))) {
        int r1 = r | (1 << Bt);
        float2 a0 = v[r], a1 = v[r1];
        v[r]  = ct ? a1 : a0;
        v[r1] = ct ? a0 : a1;
    }
}

template<int Bc, int LBt>
__device__ __forceinline__ void cnot_lc(float2 (&v)[8]) {
#pragma unroll
    for (int r = 0; r < 8; r++) if ((r >> Bc) & 1) {
        v[r] = shfl2(v[r], 1 << LBt);
    }
}

template<int Bc, int Bt>
__device__ __forceinline__ void cnot_ll(float2 (&v)[8]) {
#pragma unroll
    for (int r = 0; r < 8; r++) if (((r >> Bc) & 1) && !((r >> Bt) & 1)) {
        int r1 = r | (1 << Bt);
        float2 t = v[r]; v[r] = v[r1]; v[r1] = t;
    }
}

// measurements (lane-bit wires only; wires 0..3 are bits 7..4 -> LB 4..1)
template<int LB>
__device__ __forceinline__ float expz_cross(const float2 (&v)[8], int lane) {
    float sg = ((lane >> LB) & 1) ? -1.0f : 1.0f;
    float acc = 0.0f;
#pragma unroll
    for (int r = 0; r < 8; r++) acc += fmaf(v[r].x, v[r].x, v[r].y * v[r].y);
    return warp_reduce(sg * acc);
}

template<int LB>
__device__ __forceinline__ float expx_cross(const float2 (&v)[8]) {
    float acc = 0.0f;
#pragma unroll
    for (int r = 0; r < 8; r++) {
        float2 o = shfl2(v[r], 1 << LB);
        acc += fmaf(v[r].x, o.x, v[r].y * o.y);
    }
    // each unordered pair counted twice across lanes; expX = 2 * sum_pairs = reduce
    return warp_reduce(acc);
}

// ---- 4-qubit (16 amp) gates on a single per-lane float2 (idx = lane & 15) ----

template<int B>
__device__ __forceinline__ void rxv(float2& a, float c, float s) {
    float2 o = shfl2(a, 1 << B);
    a = rxmix(a, o, c, s);
}

template<int B>
__device__ __forceinline__ void rzv(float2& a, float c, float s, int idx) {
    float sgn = ((idx >> B) & 1) ? s : -s;
    a = make_float2(fmaf(c, a.x, -sgn * a.y), fmaf(c, a.y, sgn * a.x));
}

template<int Bc, int Bt>
__device__ __forceinline__ void crxv(float2& a, float c, float s, int idx) {
    float2 o = shfl2(a, 1 << Bt);
    float2 m = rxmix(a, o, c, s);
    a = ((idx >> Bc) & 1) ? m : a;
}

template<int Bc, int Bt>
__device__ __forceinline__ void cnotv(float2& a, int idx) {
    float2 o = shfl2(a, 1 << Bt);
    a = ((idx >> Bc) & 1) ? o : a;
}

template<int B>
__device__ __forceinline__ float expzv(float2 a, int idx) {
    float sg = ((idx >> B) & 1) ? -1.0f : 1.0f;
    return 0.5f * warp_reduce(sg * fmaf(a.x, a.x, a.y * a.y));  // /2: state duplicated in halves
}

template<int B>
__device__ __forceinline__ float expxv(float2 a) {
    float2 o = shfl2(a, 1 << B);
    // pairs counted 2x per half-warp group and the state is duplicated -> reduce = 4*sum_pairs;
    // expX = 2*sum_pairs = reduce/2
    return 0.5f * warp_reduce(fmaf(a.x, o.x, a.y * o.y));
}

// ---- main kernel ----

__global__ __launch_bounds__(32 * WPB)
void qattn_kernel(const float* __restrict__ x1, const float* __restrict__ x2,
                  const float* __restrict__ W, const float* __restrict__ bvec,
                  const float* __restrict__ score_gates,
                  float* __restrict__ out, int B) {
    const int warp = threadIdx.x >> 5;
    const int lane = threadIdx.x & 31;
    const int s = blockIdx.x * WPB + warp;
    if (s >= B) return;

    // ---- projections xq = x1@W.T + b, xk = x2@W.T + b ----
    const float* r1 = x1 + (size_t)s * IN_DIM;
    const float* r2 = x2 + (size_t)s * IN_DIM;
    float a1 = r1[lane], a2 = r1[lane + 32], a3 = r1[lane + 64];
    float b1 = r2[lane], b2 = r2[lane + 32], b3 = r2[lane + 64];
    float xq[4], xk[4];
#pragma unroll
    for (int i = 0; i < 4; i++) {
        const float* wr = W + i * IN_DIM;
        float w1 = wr[lane], w2 = wr[lane + 32], w3 = wr[lane + 64];
        float pq = warp_reduce(fmaf(a1, w1, fmaf(a2, w2, a3 * w3)));
        float pk = warp_reduce(fmaf(b1, w1, fmaf(b2, w2, b3 * w3)));
        xq[i] = pq + bvec[i];
        xk[i] = pk + bvec[i];
    }

    // =================== score circuit: 8 wires (wire w -> bit 7-w) ===================
    float2 v[8];
#pragma unroll
    for (int r = 0; r < 8; r++) v[r] = make_float2(0.0f, 0.0f);
    if (lane == 0) v[0].x = 1.0f;

    // AngleEmbedding RX(xq[i]) on wires 0..3 -> bits 7..4 -> LB 4..1
    {
        float c, sn;
        __sincosf(0.5f * xq[0], &sn, &c); rx_cross<4>(v, c, sn);
        __sincosf(0.5f * xq[1], &sn, &c); rx_cross<3>(v, c, sn);
        __sincosf(0.5f * xq[2], &sn, &c); rx_cross<2>(v, c, sn);
        __sincosf(0.5f * xq[3], &sn, &c); rx_cross<1>(v, c, sn);
    }

    // init_qkv q (wires 0..3): rot layer
    {
        float2 t;
        t = trig(T_WQ_ROT + 0);  rz_cross<4>(v, t.x, t.y, lane);
        t = trig(T_WQ_ROT + 1);  rx_cross<4>(v, t.x, t.y);
        t = trig(T_WQ_ROT + 2);  rz_cross<4>(v, t.x, t.y, lane);
        t = trig(T_WQ_ROT + 3);  rz_cross<3>(v, t.x, t.y, lane);
        t = trig(T_WQ_ROT + 4);  rx_cross<3>(v, t.x, t.y);
        t = trig(T_WQ_ROT + 5);  rz_cross<3>(v, t.x, t.y, lane);
        t = trig(T_WQ_ROT + 6);  rz_cross<2>(v, t.x, t.y, lane);
        t = trig(T_WQ_ROT + 7);  rx_cross<2>(v, t.x, t.y);
        t = trig(T_WQ_ROT + 8);  rz_cross<2>(v, t.x, t.y, lane);
        t = trig(T_WQ_ROT + 9);  rz_cross<1>(v, t.x, t.y, lane);
        t = trig(T_WQ_ROT + 10); rx_cross<1>(v, t.x, t.y);
        t = trig(T_WQ_ROT + 11); rz_cross<1>(v, t.x, t.y, lane);
        // CRX ring: (b7->b6),(b6->b5),(b5->b4),(b4->b7) -> LB pairs
        t = trig(T_WQ_CRX + 0); crx_cc<4, 3>(v, t.x, t.y, lane);
        t = trig(T_WQ_CRX + 1); crx_cc<3, 2>(v, t.x, t.y, lane);
        t = trig(T_WQ_CRX + 2); crx_cc<2, 1>(v, t.x, t.y, lane);
        t = trig(T_WQ_CRX + 3); crx_cc<1, 4>(v, t.x, t.y, lane);
        // CNOT ring
        cnot_cc<4, 3>(v, lane);
        cnot_cc<3, 2>(v, lane);
        cnot_cc<2, 1>(v, lane);
        cnot_cc<1, 4>(v, lane);
    }

    // AngleEmbedding RX(xk[i]) on wires 4..7 -> bits 3..0 (bit3 = LB0 cross; bits 2..0 local)
    float2 eck[4];
    {
        float c, sn;
        __sincosf(0.5f * xk[0], &sn, &c); eck[0] = make_float2(c, sn); rx_cross<0>(v, c, sn);
        __sincosf(0.5f * xk[1], &sn, &c); eck[1] = make_float2(c, sn); rx_local<2>(v, c, sn);
        __sincosf(0.5f * xk[2], &sn, &c); eck[2] = make_float2(c, sn); rx_local<1>(v, c, sn);
        __sincosf(0.5f * xk[3], &sn, &c); eck[3] = make_float2(c, sn); rx_local<0>(v, c, sn);
    }

    // init_qkv k (wires 4..7): rot layer on bits 3..0
    {
        float2 t;
        t = trig(T_WK_ROT + 0);  rz_cross<0>(v, t.x, t.y, lane);
        t = trig(T_WK_ROT + 1);  rx_cross<0>(v, t.x, t.y);
        t = trig(T_WK_ROT + 2);  rz_cross<0>(v, t.x, t.y, lane);
        t = trig(T_WK_ROT + 3);  rz_local<2>(v, t.x, t.y);
        t = trig(T_WK_ROT + 4);  rx_local<2>(v, t.x, t.y);
        t = trig(T_WK_ROT + 5);  rz_local<2>(v, t.x, t.y);
        t = trig(T_WK_ROT + 6);  rz_local<1>(v, t.x, t.y);
        t = trig(T_WK_ROT + 7);  rx_local<1>(v, t.x, t.y);
        t = trig(T_WK_ROT + 8);  rz_local<1>(v, t.x, t.y);
        t = trig(T_WK_ROT + 9);  rz_local<0>(v, t.x, t.y);
        t = trig(T_WK_ROT + 10); rx_local<0>(v, t.x, t.y);
        t = trig(T_WK_ROT + 11); rz_local<0>(v, t.x, t.y);
        // CRX ring: (b3->b2),(b2->b1),(b1->b0),(b0->b3)
        t = trig(T_WK_CRX + 0); crx_cl<0, 2>(v, t.x, t.y, lane);
        t = trig(T_WK_CRX + 1); crx_ll<2, 1>(v, t.x, t.y);
        t = trig(T_WK_CRX + 2); crx_ll<1, 0>(v, t.x, t.y);
        t = trig(T_WK_CRX + 3); crx_lc<0, 0>(v, t.x, t.y);
        // CNOT ring
        cnot_cl<0, 2>(v, lane);
        cnot_ll<2, 1>(v);
        cnot_ll<1, 0>(v);
        cnot_lc<0, 0>(v);
    }

    // cross CRX (interleaved order as reference): control wire i -> bit 7-i, target wire i+4 -> bit 3-i
    {
        float2 t;
        t = trig(T_WC_CRX + 0); crx_cc<4, 0>(v, t.x, t.y, lane);
        t = trig(T_WC_CRX + 4); crx_cc<0, 4>(v, t.x, t.y, lane);
        t = trig(T_WC_CRX + 1); crx_cl<3, 2>(v, t.x, t.y, lane);
        t = trig(T_WC_CRX + 5); crx_lc<2, 3>(v, t.x, t.y);
        t = trig(T_WC_CRX + 2); crx_cl<2, 1>(v, t.x, t.y, lane);
        t = trig(T_WC_CRX + 6); crx_lc<1, 2>(v, t.x, t.y);
        t = trig(T_WC_CRX + 3); crx_cl<1, 0>(v, t.x, t.y, lane);
        t = trig(T_WC_CRX + 7); crx_lc<0, 1>(v, t.x, t.y);
    }
    // cross CNOT (interleaved)
    cnot_cc<4, 0>(v, lane);  cnot_cc<0, 4>(v, lane);
    cnot_cl<3, 2>(v, lane);  cnot_lc<2, 3>(v);
    cnot_cl<2, 1>(v, lane);  cnot_lc<1, 2>(v);
    cnot_cl<1, 0>(v, lane);  cnot_lc<0, 1>(v);

    // final rot layer on wires 0..3 -> LB 4..1
    {
        float2 t;
        t = trig(T_WC_ROT + 0);  rz_cross<4>(v, t.x, t.y, lane);
        t = trig(T_WC_ROT + 1);  rx_cross<4>(v, t.x, t.y);
        t = trig(T_WC_ROT + 2);  rz_cross<4>(v, t.x, t.y, lane);
        t = trig(T_WC_ROT + 3);  rz_cross<3>(v, t.x, t.y, lane);
        t = trig(T_WC_ROT + 4);  rx_cross<3>(v, t.x, t.y);
        t = trig(T_WC_ROT + 5);  rz_cross<3>(v, t.x, t.y, lane);
        t = trig(T_WC_ROT + 6);  rz_cross<2>(v, t.x, t.y, lane);
        t = trig(T_WC_ROT + 7);  rx_cross<2>(v, t.x, t.y);
        t = trig(T_WC_ROT + 8);  rz_cross<2>(v, t.x, t.y, lane);
        t = trig(T_WC_ROT + 9);  rz_cross<1>(v, t.x, t.y, lane);
        t = trig(T_WC_ROT + 10); rx_cross<1>(v, t.x, t.y);
        t = trig(T_WC_ROT + 11); rz_cross<1>(v, t.x, t.y, lane);
    }

    // measurements on wires 0..3 -> LB 4..1
    float score[4];
    {
        float z, xe;
        z = expz_cross<4>(v, lane); xe = expx_cross<4>(v); score[0] = sqrtf(fmaf(z, z, xe * xe));
        z = expz_cross<3>(v, lane); xe = expx_cross<3>(v); score[1] = sqrtf(fmaf(z, z, xe * xe));
        z = expz_cross<2>(v, lane); xe = expx_cross<2>(v); score[2] = sqrtf(fmaf(z, z, xe * xe));
        z = expz_cross<1>(v, lane); xe = expx_cross<1>(v); score[3] = sqrtf(fmaf(z, z, xe * xe));
    }

    // =================== value circuit: 4 wires (wire w -> bit 3-w), idx = lane & 15 ===================
    const int idx = lane & 15;
    float2 a = make_float2(idx == 0 ? 1.0f : 0.0f, 0.0f);

    // embed RX(xk[i]) on bit 3-i (reuse cached trig)
    rxv<3>(a, eck[0].x, eck[0].y);
    rxv<2>(a, eck[1].x, eck[1].y);
    rxv<1>(a, eck[2].x, eck[2].y);
    rxv<0>(a, eck[3].x, eck[3].y);

    // init_qkv v: rot layer on bits 3..0
    {
        float2 t;
        t = trig(T_WV_ROT + 0);  rzv<3>(a, t.x, t.y, idx);
        t = trig(T_WV_ROT + 1);  rxv<3>(a, t.x, t.y);
        t = trig(T_WV_ROT + 2);  rzv<3>(a, t.x, t.y, idx);
        t = trig(T_WV_ROT + 3);  rzv<2>(a, t.x, t.y, idx);
        t = trig(T_WV_ROT + 4);  rxv<2>(a, t.x, t.y);
        t = trig(T_WV_ROT + 5);  rzv<2>(a, t.x, t.y, idx);
        t = trig(T_WV_ROT + 6);  rzv<1>(a, t.x, t.y, idx);
        t = trig(T_WV_ROT + 7);  rxv<1>(a, t.x, t.y);
        t = trig(T_WV_ROT + 8);  rzv<1>(a, t.x, t.y, idx);
        t = trig(T_WV_ROT + 9);  rzv<0>(a, t.x, t.y, idx);
        t = trig(T_WV_ROT + 10); rxv<0>(a, t.x, t.y);
        t = trig(T_WV_ROT + 11); rzv<0>(a, t.x, t.y, idx);
        // CRX ring (b3->b2),(b2->b1),(b1->b0),(b0->b3)
        t = trig(T_WV_CRX + 0); crxv<3, 2>(a, t.x, t.y, idx);
        t = trig(T_WV_CRX + 1); crxv<2, 1>(a, t.x, t.y, idx);
        t = trig(T_WV_CRX + 2); crxv<1, 0>(a, t.x, t.y, idx);
        t = trig(T_WV_CRX + 3); crxv<0, 3>(a, t.x, t.y, idx);
        // CNOT ring
        cnotv<3, 2>(a, idx);
        cnotv<2, 1>(a, idx);
        cnotv<1, 0>(a, idx);
        cnotv<0, 3>(a, idx);
    }

    // score-modulated RX: theta = tanh(score[i]) * score_gates[i] on bit 3-i
    {
        float c, sn;
        __sincosf(0.5f * tanhf(score[0]) * __ldg(score_gates + 0), &sn, &c); rxv<3>(a, c, sn);
        __sincosf(0.5f * tanhf(score[1]) * __ldg(score_gates + 1), &sn, &c); rxv<2>(a, c, sn);
        __sincosf(0.5f * tanhf(score[2]) * __ldg(score_gates + 2), &sn, &c); rxv<1>(a, c, sn);
        __sincosf(0.5f * tanhf(score[3]) * __ldg(score_gates + 3), &sn, &c); rxv<0>(a, c, sn);
    }

    // final CNOT ring
    cnotv<3, 2>(a, idx);
    cnotv<2, 1>(a, idx);
    cnotv<1, 0>(a, idx);
    cnotv<0, 3>(a, idx);

    // measurements: wire i -> bit 3-i ; out = [z0..z3, x0..x3]
    float zout[4], xout[4];
    zout[0] = expzv<3>(a, idx); xout[0] = expxv<3>(a);
    zout[1] = expzv<2>(a, idx); xout[1] = expxv<2>(a);
    zout[2] = expzv<1>(a, idx); xout[2] = expxv<1>(a);
    zout[3] = expzv<0>(a, idx); xout[3] = expxv<0>(a);

    if (lane == 0) {
        float* o = out + (size_t)s * 8;
#pragma unroll
        for (int i = 0; i < 4; i++) { o[i] = zout[i]; o[4 + i] = xout[i]; }
    }
}

extern "C" void kernel_launch(void* const* d_in, const int* in_sizes, int n_in,
                              void* d_out, int out_size) {
    const float* x1          = (const float*)d_in[0];
    const float* x2          = (const float*)d_in[1];
    const float* W           = (const float*)d_in[2];
    const float* b           = (const float*)d_in[3];
    const float* wq_rot      = (const float*)d_in[4];
    const float* wq_crx      = (const float*)d_in[5];
    const float* wk_rot      = (const float*)d_in[6];
    const float* wk_crx      = (const float*)d_in[7];
    const float* wv_rot      = (const float*)d_in[8];
    const float* wv_crx      = (const float*)d_in[9];
    const float* wc_rot      = (const float*)d_in[10];
    const float* wc_crx      = (const float*)d_in[11];
    const float* score_gates = (const float*)d_in[12];

    int B = in_sizes[0] / IN_DIM;
    prep_kernel<<<1, 68>>>(wq_rot, wq_crx, wk_rot, wk_crx, wv_rot, wv_crx, wc_rot, wc_crx);
    int blocks = (B + WPB - 1) / WPB;
    qattn_kernel<<<blocks, 32 * WPB>>>(x1, x2, W, b, score_gates, (float*)d_out, B);
}